// round 1
// baseline (speedup 1.0000x reference)
#include <cuda_runtime.h>
#include <cuda_bf16.h>

// Problem constants
#define BQ   4096
#define NQ   32
#define HQ   256
#define DINQ 256
#define RQ   3
#define KQ   (DINQ + HQ)   // 512
#define SPAD 260           // smem row stride (floats), 16B-aligned, tolerable 4-way conflicts
#define VIRTUAL_DECAY 0.7f
#define MB   8             // batches per CTA in gate kernel

// -------- device scratch (no dynamic allocation allowed) --------
__device__ float g_WfT[RQ * HQ * HQ];   // [r][h][g]
__device__ float g_WiT[KQ * HQ];        // [k][g]
__device__ float g_WoT[KQ * HQ];
__device__ float g_WuT[KQ * HQ];
__device__ float g_hs[BQ * HQ];         // child_h_sum
__device__ float g_cs[BQ * HQ];         // child_c_sum

// -------- prep: transpose W_f (R,H,H)[r][g][h] -> [r][h][g] --------
__global__ void transpose_wf_kernel(const float* __restrict__ Wf) {
    int idx = blockIdx.x * blockDim.x + threadIdx.x;   // over R*H*H
    if (idx >= RQ * HQ * HQ) return;
    int h = idx & (HQ - 1);
    int g = (idx >> 8) & (HQ - 1);
    int r = idx >> 16;
    g_WfT[(r * HQ + h) * HQ + g] = Wf[idx];            // Wf[r][g][h]
}

// -------- prep: transpose gate weights (H, K)[g][k] -> [k][g] --------
__global__ void transpose_gates_kernel(const float* __restrict__ Wi,
                                       const float* __restrict__ Wo,
                                       const float* __restrict__ Wu) {
    int idx = blockIdx.x * blockDim.x + threadIdx.x;   // over K*H, dst-major
    if (idx >= KQ * HQ) return;
    int g = idx & (HQ - 1);
    int k = idx >> 8;
    g_WiT[idx] = Wi[g * KQ + k];
    g_WoT[idx] = Wo[g * KQ + k];
    g_WuT[idx] = Wu[g * KQ + k];
}

// -------- kernel A: per-batch child aggregation --------
// smem layout (floats):
//   [0,      8320)  sch : 32 x 260  (decayed child_h, later reused for f)
//   [8320,  16640)  scc : 32 x 260  (decayed child_c)
//   [16640, 16672)  s_sc: scores -> attn
//   [16672, 16704)  s_dec
//   [16704, 16736)  s_rel (int)
//   [16736, 16740)  flags (int): odd, fpat
#define SMEMA_FLOATS 16740

extern __shared__ float smemA[];

__global__ __launch_bounds__(256) void childsum_kernel(
    const float* __restrict__ child_h, const float* __restrict__ child_c,
    const int*   __restrict__ rel_ids, const void* __restrict__ vmask,
    const float* __restrict__ rel_emb, const float* __restrict__ w_att,
    const float* __restrict__ b_att,   const float* __restrict__ b_f)
{
    float* sch   = smemA;
    float* scc   = smemA + NQ * SPAD;
    float* s_sc  = smemA + 2 * NQ * SPAD;
    float* s_dec = s_sc + 32;
    int*   s_rel   = (int*)(s_dec + 32);
    int*   s_flags = s_rel + 32;

    const int b    = blockIdx.x;
    const int tid  = threadIdx.x;
    const int warp = tid >> 5;
    const int lane = tid & 31;

    // ---- detect virtual_mask storage dtype (u8 vs i32 vs f32) ----
    if (tid < 2) s_flags[tid] = 0;
    __syncthreads();
    {
        const unsigned char* mb = (const unsigned char*)vmask;
        for (int off = tid; off < 8192; off += 256) {
            int m = off & 3;
            unsigned char v = mb[off];
            if (m && v) {
                s_flags[0] = 1;                                   // non-aligned nonzero byte
                if ((m == 2 && v == 0x80u) || (m == 3 && v == 0x3Fu))
                    s_flags[1] = 1;                               // looks like 1.0f pattern
            }
        }
    }
    __syncthreads();
    const int mmode = s_flags[1] ? 2 : (s_flags[0] ? 1 : 0);      // 0=i32, 1=u8, 2=f32

    // ---- relations + decay ----
    if (tid < NQ) {
        int i = b * NQ + tid;
        s_rel[tid] = rel_ids[i];
        bool mv;
        if (mmode == 0)      mv = ((const int*)vmask)[i] != 0;
        else if (mmode == 1) mv = ((const unsigned char*)vmask)[i] != 0;
        else                 mv = ((const float*)vmask)[i] != 0.0f;
        s_dec[tid] = mv ? VIRTUAL_DECAY : 1.0f;
    }
    __syncthreads();

    // ---- stage ch, cc with decay (vectorized) ----
    {
        const float4* gh = (const float4*)(child_h + (size_t)b * NQ * HQ);
        const float4* gc = (const float4*)(child_c + (size_t)b * NQ * HQ);
        for (int v = tid; v < NQ * HQ / 4; v += 256) {
            int n  = v >> 6;           // 64 float4 per row
            int h4 = v & 63;
            float d = s_dec[n];
            float4 a = gh[v];
            a.x *= d; a.y *= d; a.z *= d; a.w *= d;
            float4 c = gc[v];
            c.x *= d; c.y *= d; c.z *= d; c.w *= d;
            *((float4*)(sch + n * SPAD + h4 * 4)) = a;
            *((float4*)(scc + n * SPAD + h4 * 4)) = c;
        }
    }
    __syncthreads();

    // ---- attention scores: warp w handles children 4w..4w+3 ----
    {
        float batt = b_att[0];
        for (int nn = warp * 4; nn < warp * 4 + 4; nn++) {
            int r = s_rel[nn];
            const float* rrow = rel_emb + r * HQ;
            const float* crow = sch + nn * SPAD;
            float p = 0.0f;
            #pragma unroll
            for (int h = lane; h < HQ; h += 32)
                p += (rrow[h] + crow[h]) * w_att[h];
            #pragma unroll
            for (int o = 16; o; o >>= 1) p += __shfl_xor_sync(0xffffffffu, p, o);
            if (lane == 0) s_sc[nn] = p + batt;
        }
    }
    __syncthreads();

    // ---- softmax over N=32 (warp 0) ----
    if (warp == 0) {
        float s = s_sc[lane];
        float m = s;
        #pragma unroll
        for (int o = 16; o; o >>= 1) m = fmaxf(m, __shfl_xor_sync(0xffffffffu, m, o));
        float e = __expf(s - m);
        float su = e;
        #pragma unroll
        for (int o = 16; o; o >>= 1) su += __shfl_xor_sync(0xffffffffu, su, o);
        s_sc[lane] = e / su;
    }
    __syncthreads();

    // ---- child_h_sum : thread g ----
    {
        float acc = 0.0f;
        #pragma unroll
        for (int nn = 0; nn < NQ; nn++) acc += s_sc[nn] * sch[nn * SPAD + tid];
        g_hs[(size_t)b * HQ + tid] = acc;
    }

    // ---- f-gate matvecs: lane = child n (relation fixed per lane), warp = 32-g slab ----
    const int n  = lane;
    const int gg = warp;
    const int r2 = s_rel[n];
    const float4* wp = (const float4*)(g_WfT + ((size_t)r2 * HQ) * HQ + gg * 32);
    const float* chrow = sch + n * SPAD;

    float facc[32];
    #pragma unroll
    for (int j = 0; j < 32; j++) facc[j] = 0.0f;

    #pragma unroll 2
    for (int h = 0; h < HQ; h++) {
        float a = chrow[h];
        #pragma unroll
        for (int j = 0; j < 8; j++) {
            float4 w = wp[j];
            facc[4 * j + 0] += a * w.x;
            facc[4 * j + 1] += a * w.y;
            facc[4 * j + 2] += a * w.z;
            facc[4 * j + 3] += a * w.w;
        }
        wp += HQ / 4;
    }
    __syncthreads();            // everyone done reading sch

    // write f into sch (reuse)
    {
        float* frow = sch + n * SPAD + gg * 32;
        #pragma unroll
        for (int j = 0; j < 8; j++)
            ((float4*)frow)[j] = make_float4(facc[4 * j + 0], facc[4 * j + 1],
                                             facc[4 * j + 2], facc[4 * j + 3]);
    }
    __syncthreads();

    // ---- child_c_sum : thread g ----
    {
        int g = tid;
        float bf0 = b_f[g], bf1 = b_f[HQ + g], bf2 = b_f[2 * HQ + g];
        float acc = 0.0f;
        #pragma unroll
        for (int nn = 0; nn < NQ; nn++) {
            int rr = s_rel[nn];
            float bf = (rr == 0) ? bf0 : ((rr == 1) ? bf1 : bf2);
            acc += (sch[nn * SPAD + g] + bf) * scc[nn * SPAD + g];
        }
        g_cs[(size_t)b * HQ + g] = acc;
    }
}

// -------- kernel B: gate GEMVs + pointwise epilogue, MB batches per CTA --------
__global__ __launch_bounds__(256) void gates_kernel(
    const float* __restrict__ input_vec,
    const float* __restrict__ b_i, const float* __restrict__ b_o,
    const float* __restrict__ b_u, float* __restrict__ out)
{
    __shared__ float comb[MB][KQ];     // broadcast reads -> no padding needed
    const int tid = threadIdx.x;
    const int b0  = blockIdx.x * MB;

    // load combined = [input_vec, child_h_sum]
    for (int v = tid; v < MB * KQ / 4; v += 256) {
        int m  = v >> 7;               // 128 float4 per row
        int k4 = v & 127;
        int bb = b0 + m;
        float4 val;
        if (k4 < 64) val = ((const float4*)(input_vec + (size_t)bb * DINQ))[k4];
        else         val = ((const float4*)(g_hs      + (size_t)bb * HQ))[k4 - 64];
        *((float4*)&comb[m][k4 * 4]) = val;
    }
    __syncthreads();

    const int g = tid;
    float ai[MB], ao[MB], au[MB];
    #pragma unroll
    for (int m = 0; m < MB; m++) { ai[m] = 0.0f; ao[m] = 0.0f; au[m] = 0.0f; }

    const float* wi = g_WiT + g;
    const float* wo = g_WoT + g;
    const float* wu = g_WuT + g;

    #pragma unroll 4
    for (int k = 0; k < KQ; k++) {
        float vi = wi[(size_t)k * HQ];
        float vo = wo[(size_t)k * HQ];
        float vu = wu[(size_t)k * HQ];
        #pragma unroll
        for (int m = 0; m < MB; m++) {
            float cm = comb[m][k];
            ai[m] += cm * vi;
            ao[m] += cm * vo;
            au[m] += cm * vu;
        }
    }

    float bi = b_i[g], bo = b_o[g], bu = b_u[g];
    #pragma unroll
    for (int m = 0; m < MB; m++) {
        int bb = b0 + m;
        float iv = 1.0f / (1.0f + __expf(-(ai[m] + bi)));
        float ov = 1.0f / (1.0f + __expf(-(ao[m] + bo)));
        float uv = tanhf(au[m] + bu);
        float c  = iv * uv + g_cs[(size_t)bb * HQ + g];
        float h  = ov * tanhf(c);
        out[(size_t)bb * HQ + g]                      = h;
        out[(size_t)BQ * HQ + (size_t)bb * HQ + g]    = c;
    }
}

// -------- launch --------
extern "C" void kernel_launch(void* const* d_in, const int* in_sizes, int n_in,
                              void* d_out, int out_size) {
    const float* input_vec = (const float*)d_in[0];
    const float* child_h   = (const float*)d_in[1];
    const float* child_c   = (const float*)d_in[2];
    const int*   rel_ids   = (const int*)  d_in[3];
    const void*  vmask     =               d_in[4];
    const float* rel_emb   = (const float*)d_in[5];
    const float* W_i       = (const float*)d_in[6];
    const float* b_i       = (const float*)d_in[7];
    const float* W_f       = (const float*)d_in[8];
    const float* b_f       = (const float*)d_in[9];
    const float* W_o       = (const float*)d_in[10];
    const float* b_o       = (const float*)d_in[11];
    const float* W_u       = (const float*)d_in[12];
    const float* b_u       = (const float*)d_in[13];
    const float* w_att     = (const float*)d_in[14];
    const float* b_att     = (const float*)d_in[15];
    float* out = (float*)d_out;

    transpose_wf_kernel<<<(RQ * HQ * HQ + 255) / 256, 256>>>(W_f);
    transpose_gates_kernel<<<(KQ * HQ + 255) / 256, 256>>>(W_i, W_o, W_u);

    size_t smemA = (size_t)SMEMA_FLOATS * sizeof(float);
    cudaFuncSetAttribute(childsum_kernel,
                         cudaFuncAttributeMaxDynamicSharedMemorySize, (int)smemA);
    childsum_kernel<<<BQ, 256, smemA>>>(child_h, child_c, rel_ids, vmask,
                                        rel_emb, w_att, b_att, b_f);

    gates_kernel<<<BQ / MB, 256>>>(input_vec, b_i, b_o, b_u, out);
}

// round 2
// speedup vs baseline: 2.4448x; 2.4448x over previous
#include <cuda_runtime.h>
#include <cuda_bf16.h>

// Problem constants
#define BQ   4096
#define NQ   32
#define HQ   256
#define DINQ 256
#define RQ   3
#define KQ   (DINQ + HQ)   // 512
#define VIRTUAL_DECAY 0.7f
#define MB   16            // batches per CTA in gate kernel

// fgate tiling
#define TH   8                       // h per weight tile
#define NT   (HQ / TH)               // 32 tiles
#define WREL (TH * HQ + 8)           // 2056 floats: per-relation block (pad -> +8 banks per r)
#define WBUF (RQ * WREL)             // 6168 floats per buffer
#define CHT_STRIDE 33
#define CHT_FLOATS (HQ * CHT_STRIDE) // 8448
#define FG_SMEM_FLOATS (CHT_FLOATS + 2 * WBUF + 64)
#define FG_SMEM_BYTES  (FG_SMEM_FLOATS * 4)

// -------- device scratch (no dynamic allocation allowed) --------
__device__ float g_WfT[RQ * HQ * HQ];   // [r][h][g]
__device__ float g_WiT[KQ * HQ];        // [k][g]
__device__ float g_WoT[KQ * HQ];
__device__ float g_WuT[KQ * HQ];
__device__ float g_hs[BQ * HQ];         // child_h_sum
__device__ float g_cs[BQ * HQ];         // child_c_sum
__device__ int   g_mmode;               // virtual_mask storage dtype

__device__ __forceinline__ float load_dec(const void* vmask, int i, int mmode) {
    bool mv;
    if (mmode == 0)      mv = ((const int*)vmask)[i] != 0;
    else if (mmode == 1) mv = ((const unsigned char*)vmask)[i] != 0;
    else                 mv = ((const float*)vmask)[i] != 0.0f;
    return mv ? VIRTUAL_DECAY : 1.0f;
}

// -------- prep: transposes + mask dtype detection (one kernel) --------
__global__ __launch_bounds__(256) void prep_kernel(
    const float* __restrict__ Wf, const float* __restrict__ Wi,
    const float* __restrict__ Wo, const float* __restrict__ Wu,
    const void* __restrict__ vmask)
{
    int idx = blockIdx.x * 256 + threadIdx.x;
    if (idx < RQ * HQ * HQ) {
        int h = idx & (HQ - 1);
        int g = (idx >> 8) & (HQ - 1);
        int r = idx >> 16;
        g_WfT[(r * HQ + h) * HQ + g] = Wf[idx];        // Wf[r][g][h]
    }
    if (idx < KQ * HQ) {
        int g = idx & (HQ - 1);
        int k = idx >> 8;
        g_WiT[idx] = Wi[g * KQ + k];
        g_WoT[idx] = Wo[g * KQ + k];
        g_WuT[idx] = Wu[g * KQ + k];
    }
    if (blockIdx.x == 0) {
        __shared__ int fl[2];
        int tid = threadIdx.x;
        if (tid < 2) fl[tid] = 0;
        __syncthreads();
        const unsigned char* mb = (const unsigned char*)vmask;
        for (int off = tid; off < 8192; off += 256) {
            int m = off & 3;
            unsigned char v = mb[off];
            if (m && v) {
                fl[0] = 1;                                     // non-aligned nonzero byte -> not i32
                if ((m == 2 && v == 0x80u) || (m == 3 && v == 0x3Fu))
                    fl[1] = 1;                                 // looks like 1.0f pattern -> f32
            }
        }
        __syncthreads();
        if (tid == 0) g_mmode = fl[1] ? 2 : (fl[0] ? 1 : 0);   // 0=i32, 1=u8, 2=f32
    }
}

// -------- fgate: copy one 8-h weight tile (all 3 relations) into smem buffer --------
__device__ __forceinline__ void issue_tile(unsigned wsm_base, int tid, int t, int buf) {
    #pragma unroll
    for (int k = 0; k < 6; k++) {
        int f4  = tid + k * 256;          // 0..1535 float4s
        int r   = f4 / 512;
        int rem = f4 - r * 512;
        int hh  = rem >> 6;
        int c4  = rem & 63;
        const float4* src = (const float4*)(g_WfT + ((size_t)r * HQ + (t * TH + hh)) * HQ) + c4;
        unsigned dst = wsm_base + (unsigned)((buf * WBUF + r * WREL + hh * HQ + c4 * 4) * 4);
        asm volatile("cp.async.cg.shared.global [%0], [%1], 16;\n" :: "r"(dst), "l"(src));
    }
    asm volatile("cp.async.commit_group;\n");
}

// -------- fgate + child_c_sum kernel (the heavy one) --------
extern __shared__ float smemF[];

__global__ __launch_bounds__(256, 2) void fgate_kernel(
    const float* __restrict__ child_h, const float* __restrict__ child_c,
    const int*   __restrict__ rel_ids, const void* __restrict__ vmask,
    const float* __restrict__ b_f)
{
    float* chT  = smemF;                        // [256 h][stride 33] decayed child_h, h-major
    float* wbuf = smemF + CHT_FLOATS;           // 2 x WBUF weight tiles
    int*   s_rel = (int*)(smemF + CHT_FLOATS + 2 * WBUF);
    float* s_dec = (float*)(s_rel + 32);

    const int b    = blockIdx.x;
    const int tid  = threadIdx.x;
    const int lane = tid & 31;
    const int warp = tid >> 5;
    const int mmode = g_mmode;

    if (tid < NQ) {
        int i = b * NQ + tid;
        s_rel[tid] = rel_ids[i];
        s_dec[tid] = load_dec(vmask, i, mmode);
    }
    __syncthreads();

    // stage decayed child_h transposed: chT[h][n]
    {
        const float4* gh = (const float4*)(child_h + (size_t)b * NQ * HQ);
        #pragma unroll
        for (int k = 0; k < 8; k++) {
            int v  = tid + k * 256;
            int n  = v >> 6;
            int h4 = v & 63;
            float d = s_dec[n];
            float4 a = gh[v];
            chT[(h4 * 4 + 0) * CHT_STRIDE + n] = a.x * d;
            chT[(h4 * 4 + 1) * CHT_STRIDE + n] = a.y * d;
            chT[(h4 * 4 + 2) * CHT_STRIDE + n] = a.z * d;
            chT[(h4 * 4 + 3) * CHT_STRIDE + n] = a.w * d;
        }
    }

    unsigned wsm_base = (unsigned)__cvta_generic_to_shared(wbuf);
    issue_tile(wsm_base, tid, 0, 0);
    __syncthreads();                 // chT staged

    const int r2 = s_rel[lane];      // lane = child, fixed relation
    float facc[32];
    #pragma unroll
    for (int j = 0; j < 32; j++) facc[j] = 0.0f;

    for (int t = 0; t < NT; t++) {
        asm volatile("cp.async.wait_group 0;\n");
        __syncthreads();             // tile t ready for everyone; everyone done with tile t-1
        if (t + 1 < NT) issue_tile(wsm_base, tid, t + 1, (t + 1) & 1);

        const float* wb = wbuf + (t & 1) * WBUF + r2 * WREL + warp * 32;
        #pragma unroll
        for (int hh = 0; hh < TH; hh++) {
            float a = chT[(t * TH + hh) * CHT_STRIDE + lane];
            const float4* w = (const float4*)(wb + hh * HQ);
            #pragma unroll
            for (int j = 0; j < 8; j++) {
                float4 ww = w[j];
                facc[4 * j + 0] += a * ww.x;
                facc[4 * j + 1] += a * ww.y;
                facc[4 * j + 2] += a * ww.z;
                facc[4 * j + 3] += a * ww.w;
            }
        }
    }
    __syncthreads();

    // write f into chT region (reuse): f_sm[g*33 + n]
    float* f_sm = chT;
    #pragma unroll
    for (int j = 0; j < 32; j++)
        f_sm[(warp * 32 + j) * CHT_STRIDE + lane] = facc[j];
    __syncthreads();

    // child_c_sum: thread g, cc read straight from global (coalesced), decay applied here
    {
        int g = tid;
        float bf0 = b_f[g], bf1 = b_f[HQ + g], bf2 = b_f[2 * HQ + g];
        const float* cc = child_c + (size_t)b * NQ * HQ + g;
        float acc = 0.0f;
        #pragma unroll
        for (int n = 0; n < NQ; n++) {
            int rr = s_rel[n];
            float bf = (rr == 0) ? bf0 : ((rr == 1) ? bf1 : bf2);
            acc += (f_sm[g * CHT_STRIDE + n] + bf) * (cc[n * HQ] * s_dec[n]);
        }
        g_cs[(size_t)b * HQ + g] = acc;
    }
}

// -------- attention + child_h_sum (light) --------
__global__ __launch_bounds__(256) void attn_kernel(
    const float* __restrict__ child_h, const int* __restrict__ rel_ids,
    const void* __restrict__ vmask,    const float* __restrict__ rel_emb,
    const float* __restrict__ w_att,   const float* __restrict__ b_att)
{
    __shared__ float s_sc[32], s_dec[32];
    __shared__ int   s_rel[32];
    const int b = blockIdx.x, tid = threadIdx.x;
    const int warp = tid >> 5, lane = tid & 31;
    const int mmode = g_mmode;

    if (tid < NQ) {
        int i = b * NQ + tid;
        s_rel[tid] = rel_ids[i];
        s_dec[tid] = load_dec(vmask, i, mmode);
    }
    __syncthreads();

    const float* chb = child_h + (size_t)b * NQ * HQ;
    float batt = b_att[0];
    for (int nn = warp * 4; nn < warp * 4 + 4; nn++) {
        const float* rrow = rel_emb + s_rel[nn] * HQ;
        const float* crow = chb + nn * HQ;
        float d = s_dec[nn];
        float p = 0.0f;
        #pragma unroll
        for (int h = lane; h < HQ; h += 32)
            p += (rrow[h] + d * crow[h]) * w_att[h];
        #pragma unroll
        for (int o = 16; o; o >>= 1) p += __shfl_xor_sync(0xffffffffu, p, o);
        if (lane == 0) s_sc[nn] = p + batt;
    }
    __syncthreads();

    if (warp == 0) {
        float s = s_sc[lane], m = s;
        #pragma unroll
        for (int o = 16; o; o >>= 1) m = fmaxf(m, __shfl_xor_sync(0xffffffffu, m, o));
        float e = __expf(s - m), su = e;
        #pragma unroll
        for (int o = 16; o; o >>= 1) su += __shfl_xor_sync(0xffffffffu, su, o);
        s_sc[lane] = e / su;
    }
    __syncthreads();

    {
        int g = tid;
        float acc = 0.0f;
        #pragma unroll
        for (int n = 0; n < NQ; n++)
            acc += s_sc[n] * s_dec[n] * chb[n * HQ + g];
        g_hs[(size_t)b * HQ + g] = acc;
    }
}

// -------- gates GEMVs + pointwise epilogue, MB batches per CTA --------
__global__ __launch_bounds__(256) void gates_kernel(
    const float* __restrict__ input_vec,
    const float* __restrict__ b_i, const float* __restrict__ b_o,
    const float* __restrict__ b_u, float* __restrict__ out)
{
    __shared__ float comb[MB][KQ];
    const int tid = threadIdx.x;
    const int b0  = blockIdx.x * MB;

    #pragma unroll
    for (int k = 0; k < MB * KQ / 4 / 256; k++) {
        int v  = tid + k * 256;
        int m  = v >> 7;                 // 128 float4 per row
        int k4 = v & 127;
        int bb = b0 + m;
        float4 val;
        if (k4 < 64) val = ((const float4*)(input_vec + (size_t)bb * DINQ))[k4];
        else         val = ((const float4*)(g_hs      + (size_t)bb * HQ))[k4 - 64];
        *((float4*)&comb[m][k4 * 4]) = val;
    }
    __syncthreads();

    const int g = tid;
    float ai[MB], ao[MB], au[MB];
    #pragma unroll
    for (int m = 0; m < MB; m++) { ai[m] = 0.0f; ao[m] = 0.0f; au[m] = 0.0f; }

    const float* wi = g_WiT + g;
    const float* wo = g_WoT + g;
    const float* wu = g_WuT + g;

    #pragma unroll 4
    for (int k = 0; k < KQ; k++) {
        float vi = wi[(size_t)k * HQ];
        float vo = wo[(size_t)k * HQ];
        float vu = wu[(size_t)k * HQ];
        #pragma unroll
        for (int m = 0; m < MB; m++) {
            float cm = comb[m][k];
            ai[m] += cm * vi;
            ao[m] += cm * vo;
            au[m] += cm * vu;
        }
    }

    float bi = b_i[g], bo = b_o[g], bu = b_u[g];
    #pragma unroll
    for (int m = 0; m < MB; m++) {
        int bb = b0 + m;
        float iv = 1.0f / (1.0f + __expf(-(ai[m] + bi)));
        float ov = 1.0f / (1.0f + __expf(-(ao[m] + bo)));
        float uv = tanhf(au[m] + bu);
        float c  = iv * uv + g_cs[(size_t)bb * HQ + g];
        float h  = ov * tanhf(c);
        out[(size_t)bb * HQ + g]                   = h;
        out[(size_t)BQ * HQ + (size_t)bb * HQ + g] = c;
    }
}

// -------- launch --------
extern "C" void kernel_launch(void* const* d_in, const int* in_sizes, int n_in,
                              void* d_out, int out_size) {
    const float* input_vec = (const float*)d_in[0];
    const float* child_h   = (const float*)d_in[1];
    const float* child_c   = (const float*)d_in[2];
    const int*   rel_ids   = (const int*)  d_in[3];
    const void*  vmask     =               d_in[4];
    const float* rel_emb   = (const float*)d_in[5];
    const float* W_i       = (const float*)d_in[6];
    const float* b_i       = (const float*)d_in[7];
    const float* W_f       = (const float*)d_in[8];
    const float* b_f       = (const float*)d_in[9];
    const float* W_o       = (const float*)d_in[10];
    const float* b_o       = (const float*)d_in[11];
    const float* W_u       = (const float*)d_in[12];
    const float* b_u       = (const float*)d_in[13];
    const float* w_att     = (const float*)d_in[14];
    const float* b_att     = (const float*)d_in[15];
    float* out = (float*)d_out;

    prep_kernel<<<(RQ * HQ * HQ + 255) / 256, 256>>>(W_f, W_i, W_o, W_u, vmask);

    cudaFuncSetAttribute(fgate_kernel,
                         cudaFuncAttributeMaxDynamicSharedMemorySize, FG_SMEM_BYTES);
    fgate_kernel<<<BQ, 256, FG_SMEM_BYTES>>>(child_h, child_c, rel_ids, vmask, b_f);

    attn_kernel<<<BQ, 256>>>(child_h, rel_ids, vmask, rel_emb, w_att, b_att);

    gates_kernel<<<BQ / MB, 256>>>(input_vec, b_i, b_o, b_u, out);
}

// round 3
// speedup vs baseline: 4.5222x; 1.8497x over previous
#include <cuda_runtime.h>
#include <cuda_bf16.h>

// Problem constants
#define BQ   4096
#define NQ   32
#define HQ   256
#define DINQ 256
#define RQ   3
#define KQ   (DINQ + HQ)   // 512
#define VIRTUAL_DECAY 0.7f
#define MB   16            // batches per CTA in gate kernel
#define ROWS_TOT (BQ * NQ) // 131072

// GEMM tiling
#define GM 128
#define GN 128
#define GK 32
#define NKS (HQ / GK)      // 8 k-steps
#define ASTR (GK + 4)      // 36
#define BSTR (GN + 4)      // 132
#define AS_FLOATS (2 * GM * ASTR)   // 9216
#define BS_FLOATS (2 * GK * BSTR)   // 8448
#define FGEMM_SMEM ((AS_FLOATS + BS_FLOATS + 128 + 128) * 4)   // ~71.7 KB

// -------- device scratch (no dynamic allocation allowed) --------
__device__ float g_WfT[RQ * HQ * HQ];   // [r][h][g]
__device__ float g_WiT[KQ * HQ];        // [k][g]
__device__ float g_WoT[KQ * HQ];
__device__ float g_WuT[KQ * HQ];
__device__ float g_hs[BQ * HQ];         // child_h_sum
__device__ float g_cs[BQ * HQ];         // child_c_sum
__device__ float g_f[(size_t)ROWS_TOT * HQ];   // f gate results, [b][n][g]
__device__ float g_dec[ROWS_TOT];       // decay per row
__device__ int   g_idxr[RQ][ROWS_TOT];  // row indices grouped by relation
__device__ int   g_cnt[RQ];
__device__ int   g_mmode;               // virtual_mask storage dtype

__device__ __forceinline__ float load_dec(const void* vmask, int i, int mmode) {
    bool mv;
    if (mmode == 0)      mv = ((const int*)vmask)[i] != 0;
    else if (mmode == 1) mv = ((const unsigned char*)vmask)[i] != 0;
    else                 mv = ((const float*)vmask)[i] != 0.0f;
    return mv ? VIRTUAL_DECAY : 1.0f;
}

// -------- prep1: transposes + mask dtype detection + zero counters --------
__global__ __launch_bounds__(256) void prep1_kernel(
    const float* __restrict__ Wf, const float* __restrict__ Wi,
    const float* __restrict__ Wo, const float* __restrict__ Wu,
    const void* __restrict__ vmask)
{
    int idx = blockIdx.x * 256 + threadIdx.x;
    if (idx < RQ * HQ * HQ) {
        int h = idx & (HQ - 1);
        int g = (idx >> 8) & (HQ - 1);
        int r = idx >> 16;
        g_WfT[(r * HQ + h) * HQ + g] = Wf[idx];        // Wf[r][g][h]
    }
    if (idx < KQ * HQ) {
        int g = idx & (HQ - 1);
        int k = idx >> 8;
        g_WiT[idx] = Wi[g * KQ + k];
        g_WoT[idx] = Wo[g * KQ + k];
        g_WuT[idx] = Wu[g * KQ + k];
    }
    if (blockIdx.x == 0) {
        __shared__ int fl[2];
        int tid = threadIdx.x;
        if (tid < 2) fl[tid] = 0;
        if (tid < RQ) g_cnt[tid] = 0;
        __syncthreads();
        const unsigned char* mb = (const unsigned char*)vmask;
        for (int off = tid; off < 8192; off += 256) {
            int m = off & 3;
            unsigned char v = mb[off];
            if (m && v) {
                fl[0] = 1;                                     // non-aligned nonzero -> not i32
                if ((m == 2 && v == 0x80u) || (m == 3 && v == 0x3Fu))
                    fl[1] = 1;                                 // 1.0f byte pattern -> f32
            }
        }
        __syncthreads();
        if (tid == 0) g_mmode = fl[1] ? 2 : (fl[0] ? 1 : 0);   // 0=i32, 1=u8, 2=f32
    }
}

// -------- prep2: decay + counting-sort rows by relation --------
__global__ __launch_bounds__(256) void prep2_kernel(
    const int* __restrict__ rel_ids, const void* __restrict__ vmask)
{
    int i = blockIdx.x * 256 + threadIdx.x;
    if (i >= ROWS_TOT) return;
    int mmode = g_mmode;
    g_dec[i] = load_dec(vmask, i, mmode);
    int r = rel_ids[i];
    int pos = atomicAdd(&g_cnt[r], 1);
    g_idxr[r][pos] = i;
}

// -------- fgemm: F_r = gather(CH)_r x W_r^T, decay applied in epilogue --------
extern __shared__ float smG[];

__global__ __launch_bounds__(256, 2) void fgemm_kernel(
    const float* __restrict__ child_h)
{
    const int bx = blockIdx.x;           // row tile
    const int by = blockIdx.y;           // g tile (0..1)
    const int bz = blockIdx.z;           // relation
    const int cnt = g_cnt[bz];
    const int row0 = bx * GM;
    if (row0 >= cnt) return;

    float* As    = smG;                              // [2][GM][ASTR]
    float* Bs    = smG + AS_FLOATS;                  // [2][GK][BSTR]
    int*   s_idx = (int*)(smG + AS_FLOATS + BS_FLOATS);
    float* s_dec = (float*)(s_idx + 128);

    const int tid = threadIdx.x;
    const int tx  = tid & 15;
    const int ty  = tid >> 4;

    if (tid < 128) {
        int rr = row0 + tid;
        if (rr >= cnt) rr = cnt - 1;
        int gi = g_idxr[bz][rr];
        s_idx[tid] = gi;
        s_dec[tid] = g_dec[gi];
    }
    __syncthreads();

    // stage one k-step into buffer buf
    auto stage = [&](int ks, int buf) {
        #pragma unroll
        for (int i = 0; i < 4; i++) {
            int v = tid + i * 256;           // 0..1023
            int m = v >> 3;                  // row in tile
            int c = v & 7;                   // float4 within 32-k chunk
            const float* src = child_h + (size_t)s_idx[m] * HQ + ks * GK + c * 4;
            unsigned dst = (unsigned)__cvta_generic_to_shared(
                As + (buf * GM + m) * ASTR + c * 4);
            asm volatile("cp.async.cg.shared.global [%0], [%1], 16;\n"
                         :: "r"(dst), "l"(src));
        }
        #pragma unroll
        for (int i = 0; i < 4; i++) {
            int v = tid + i * 256;
            int k = v >> 5;                  // k row
            int c = v & 31;                  // float4 within 128-g
            const float* src = g_WfT + ((size_t)(bz * HQ + ks * GK + k)) * HQ + by * GN + c * 4;
            unsigned dst = (unsigned)__cvta_generic_to_shared(
                Bs + (buf * GK + k) * BSTR + c * 4);
            asm volatile("cp.async.cg.shared.global [%0], [%1], 16;\n"
                         :: "r"(dst), "l"(src));
        }
        asm volatile("cp.async.commit_group;\n");
    };

    float acc[64];
    #pragma unroll
    for (int i = 0; i < 64; i++) acc[i] = 0.0f;

    stage(0, 0);

    for (int ks = 0; ks < NKS; ks++) {
        if (ks + 1 < NKS) {
            stage(ks + 1, (ks + 1) & 1);
            asm volatile("cp.async.wait_group 1;\n");
        } else {
            asm volatile("cp.async.wait_group 0;\n");
        }
        __syncthreads();

        const float* Ab = As + (ks & 1) * GM * ASTR;
        const float* Bb = Bs + (ks & 1) * GK * BSTR;

        #pragma unroll 8
        for (int kk = 0; kk < GK; kk++) {
            float a[8], bv[8];
            #pragma unroll
            for (int j = 0; j < 4; j++) {
                a[j]     = Ab[(ty * 4 + j) * ASTR + kk];
                a[j + 4] = Ab[(64 + ty * 4 + j) * ASTR + kk];
            }
            float4 b0 = *(const float4*)(Bb + kk * BSTR + tx * 4);
            float4 b1 = *(const float4*)(Bb + kk * BSTR + 64 + tx * 4);
            bv[0] = b0.x; bv[1] = b0.y; bv[2] = b0.z; bv[3] = b0.w;
            bv[4] = b1.x; bv[5] = b1.y; bv[6] = b1.z; bv[7] = b1.w;
            #pragma unroll
            for (int i = 0; i < 8; i++)
                #pragma unroll
                for (int j = 0; j < 8; j++)
                    acc[i * 8 + j] += a[i] * bv[j];
        }
        __syncthreads();
    }

    // epilogue: scale by decay, scatter to g_f[row][g]
    #pragma unroll
    for (int i = 0; i < 8; i++) {
        int m = (i < 4) ? (ty * 4 + i) : (64 + ty * 4 + (i - 4));
        if (row0 + m < cnt) {
            int   row = s_idx[m];
            float d   = s_dec[m];
            float* dst = g_f + (size_t)row * HQ + by * GN;
            float4 v0 = make_float4(acc[i*8+0]*d, acc[i*8+1]*d, acc[i*8+2]*d, acc[i*8+3]*d);
            float4 v1 = make_float4(acc[i*8+4]*d, acc[i*8+5]*d, acc[i*8+6]*d, acc[i*8+7]*d);
            *(float4*)(dst + tx * 4)      = v0;
            *(float4*)(dst + 64 + tx * 4) = v1;
        }
    }
}

// -------- combine: attention + child_h_sum + child_c_sum --------
__global__ __launch_bounds__(256) void combine_kernel(
    const float* __restrict__ child_h, const float* __restrict__ child_c,
    const int*   __restrict__ rel_ids, const float* __restrict__ rel_emb,
    const float* __restrict__ w_att,   const float* __restrict__ b_att,
    const float* __restrict__ b_f)
{
    __shared__ float sch[NQ][264];        // decayed child_h
    __shared__ float s_sc[32], s_dec[32];
    __shared__ int   s_rel[32];

    const int b = blockIdx.x, tid = threadIdx.x;
    const int warp = tid >> 5, lane = tid & 31;

    if (tid < NQ) {
        int i = b * NQ + tid;
        s_rel[tid] = rel_ids[i];
        s_dec[tid] = g_dec[i];
    }
    __syncthreads();

    // stage decayed ch
    {
        const float4* gh = (const float4*)(child_h + (size_t)b * NQ * HQ);
        #pragma unroll
        for (int k = 0; k < 8; k++) {
            int v  = tid + k * 256;
            int n  = v >> 6;
            int h4 = v & 63;
            float d = s_dec[n];
            float4 a = gh[v];
            a.x *= d; a.y *= d; a.z *= d; a.w *= d;
            *((float4*)&sch[n][h4 * 4]) = a;
        }
    }
    __syncthreads();

    // attention scores
    {
        float batt = b_att[0];
        for (int nn = warp * 4; nn < warp * 4 + 4; nn++) {
            const float* rrow = rel_emb + s_rel[nn] * HQ;
            float p = 0.0f;
            #pragma unroll
            for (int h = lane; h < HQ; h += 32)
                p += (rrow[h] + sch[nn][h]) * w_att[h];
            #pragma unroll
            for (int o = 16; o; o >>= 1) p += __shfl_xor_sync(0xffffffffu, p, o);
            if (lane == 0) s_sc[nn] = p + batt;
        }
    }
    __syncthreads();

    if (warp == 0) {
        float s = s_sc[lane], m = s;
        #pragma unroll
        for (int o = 16; o; o >>= 1) m = fmaxf(m, __shfl_xor_sync(0xffffffffu, m, o));
        float e = __expf(s - m), su = e;
        #pragma unroll
        for (int o = 16; o; o >>= 1) su += __shfl_xor_sync(0xffffffffu, su, o);
        s_sc[lane] = e / su;
    }
    __syncthreads();

    // sums: thread g
    {
        int g = tid;
        float bf0 = b_f[g], bf1 = b_f[HQ + g], bf2 = b_f[2 * HQ + g];
        const float* cc = child_c + (size_t)b * NQ * HQ + g;
        const float* ff = g_f + (size_t)b * NQ * HQ + g;
        float hacc = 0.0f, cacc = 0.0f;
        #pragma unroll 4
        for (int n = 0; n < NQ; n++) {
            hacc += s_sc[n] * sch[n][g];
            int rr = s_rel[n];
            float bf = (rr == 0) ? bf0 : ((rr == 1) ? bf1 : bf2);
            cacc += (ff[n * HQ] + bf) * (cc[n * HQ] * s_dec[n]);
        }
        g_hs[(size_t)b * HQ + g] = hacc;
        g_cs[(size_t)b * HQ + g] = cacc;
    }
}

// -------- gates GEMVs + pointwise epilogue, MB batches per CTA --------
__global__ __launch_bounds__(256) void gates_kernel(
    const float* __restrict__ input_vec,
    const float* __restrict__ b_i, const float* __restrict__ b_o,
    const float* __restrict__ b_u, float* __restrict__ out)
{
    __shared__ float comb[MB][KQ];
    const int tid = threadIdx.x;
    const int b0  = blockIdx.x * MB;

    #pragma unroll
    for (int k = 0; k < MB * KQ / 4 / 256; k++) {
        int v  = tid + k * 256;
        int m  = v >> 7;
        int k4 = v & 127;
        int bb = b0 + m;
        float4 val;
        if (k4 < 64) val = ((const float4*)(input_vec + (size_t)bb * DINQ))[k4];
        else         val = ((const float4*)(g_hs      + (size_t)bb * HQ))[k4 - 64];
        *((float4*)&comb[m][k4 * 4]) = val;
    }
    __syncthreads();

    const int g = tid;
    float ai[MB], ao[MB], au[MB];
    #pragma unroll
    for (int m = 0; m < MB; m++) { ai[m] = 0.0f; ao[m] = 0.0f; au[m] = 0.0f; }

    const float* wi = g_WiT + g;
    const float* wo = g_WoT + g;
    const float* wu = g_WuT + g;

    #pragma unroll 4
    for (int k = 0; k < KQ; k++) {
        float vi = wi[(size_t)k * HQ];
        float vo = wo[(size_t)k * HQ];
        float vu = wu[(size_t)k * HQ];
        #pragma unroll
        for (int m = 0; m < MB; m++) {
            float cm = comb[m][k];
            ai[m] += cm * vi;
            ao[m] += cm * vo;
            au[m] += cm * vu;
        }
    }

    float bi = b_i[g], bo = b_o[g], bu = b_u[g];
    #pragma unroll
    for (int m = 0; m < MB; m++) {
        int bb = b0 + m;
        float iv = 1.0f / (1.0f + __expf(-(ai[m] + bi)));
        float ov = 1.0f / (1.0f + __expf(-(ao[m] + bo)));
        float uv = tanhf(au[m] + bu);
        float c  = iv * uv + g_cs[(size_t)bb * HQ + g];
        float h  = ov * tanhf(c);
        out[(size_t)bb * HQ + g]                   = h;
        out[(size_t)BQ * HQ + (size_t)bb * HQ + g] = c;
    }
}

// -------- launch --------
extern "C" void kernel_launch(void* const* d_in, const int* in_sizes, int n_in,
                              void* d_out, int out_size) {
    const float* input_vec = (const float*)d_in[0];
    const float* child_h   = (const float*)d_in[1];
    const float* child_c   = (const float*)d_in[2];
    const int*   rel_ids   = (const int*)  d_in[3];
    const void*  vmask     =               d_in[4];
    const float* rel_emb   = (const float*)d_in[5];
    const float* W_i       = (const float*)d_in[6];
    const float* b_i       = (const float*)d_in[7];
    const float* W_f       = (const float*)d_in[8];
    const float* b_f       = (const float*)d_in[9];
    const float* W_o       = (const float*)d_in[10];
    const float* b_o       = (const float*)d_in[11];
    const float* W_u       = (const float*)d_in[12];
    const float* b_u       = (const float*)d_in[13];
    const float* w_att     = (const float*)d_in[14];
    const float* b_att     = (const float*)d_in[15];
    float* out = (float*)d_out;

    prep1_kernel<<<(RQ * HQ * HQ + 255) / 256, 256>>>(W_f, W_i, W_o, W_u, vmask);
    prep2_kernel<<<ROWS_TOT / 256, 256>>>(rel_ids, vmask);

    cudaFuncSetAttribute(fgemm_kernel,
                         cudaFuncAttributeMaxDynamicSharedMemorySize, FGEMM_SMEM);
    dim3 ggrid((ROWS_TOT + GM - 1) / GM, HQ / GN, RQ);
    fgemm_kernel<<<ggrid, 256, FGEMM_SMEM>>>(child_h);

    combine_kernel<<<BQ, 256>>>(child_h, child_c, rel_ids, rel_emb,
                                w_att, b_att, b_f);

    gates_kernel<<<BQ / MB, 256>>>(input_vec, b_i, b_o, b_u, out);
}